// round 3
// baseline (speedup 1.0000x reference)
#include <cuda_runtime.h>

#define N_Z    8192
#define N_E    16384
#define M_PER  1024        // M // N_EMB
#define TPB    256
#define COLS   2           // columns per thread
#define ICHUNK 512
#define NCHUNK (N_Z / ICHUNK)   // 16

// Scratch (no device allocation allowed -> __device__ globals)
__device__ float4 g_zp[N_Z];              // (a_i, b0_i, b1_i, -) ; all pre-scaled by alpha*log2e
__device__ float4 g_ep[N_E];              // (e0_j, e1_j, c_j, -)
__device__ float  g_part[NCHUNK * N_E];   // per-(ichunk, column) partial sums
__device__ float  g_lse[N_E];             // per-column logsumexp

__device__ __forceinline__ float ex2(float x) {
    float r;
    asm("ex2.approx.f32 %0, %1;" : "=f"(r) : "f"(x));
    return r;
}

// ---------------------------------------------------------------------------
// Prep: build e points + fold all constants into per-row/per-col coefficients
//   arg(i,j) = a_i + c_j + b0_i*e0_j + b1_i*e1_j   (already in log2 domain)
// ---------------------------------------------------------------------------
__global__ void prep_kernel(const float* __restrict__ z,
                            const float* __restrict__ emb,
                            const float* __restrict__ log_sigma,
                            const float* __restrict__ eps,
                            const float* __restrict__ temp) {
    int i = blockIdx.x * blockDim.x + threadIdx.x;
    float T  = temp[0];
    float ls = log_sigma[0];
    float sigma = expf(ls);
    float alpha = -1.0f / (2.0f * sigma * sigma);
    const float LOG2E = 1.4426950408889634f;
    float al = alpha * LOG2E;

    if (i < N_E) {
        int k = i >> 10;            // embedding index (M_PER = 1024)
        int m = i & (M_PER - 1);    // eps index
        float e0 = (1.0f - T) * emb[2 * k + 0] + T * eps[2 * m + 0];
        float e1 = (1.0f - T) * emb[2 * k + 1] + T * eps[2 * m + 1];
        float c  = al * (e0 * e0 + e1 * e1);
        g_ep[i] = make_float4(e0, e1, c, 0.0f);
    }
    if (i < N_Z) {
        float z0 = z[2 * i + 0];
        float z1 = z[2 * i + 1];
        float a  = al * (z0 * z0 + z1 * z1);
        g_zp[i] = make_float4(a, -2.0f * al * z0, -2.0f * al * z1, 0.0f);
    }
}

// ---------------------------------------------------------------------------
// Main: each thread owns 2 columns, loops an ICHUNK of i staged in shared.
// MUFU.EX2-bound by design; fma pipe carries the 2 FFMA + 2 FADD per element.
// ---------------------------------------------------------------------------
__global__ void __launch_bounds__(TPB) main_kernel() {
    __shared__ float4 s_zp[ICHUNK];

    int colBase = blockIdx.x * (TPB * COLS);
    int ibase   = blockIdx.y * ICHUNK;

    for (int t = threadIdx.x; t < ICHUNK; t += TPB)
        s_zp[t] = g_zp[ibase + t];
    __syncthreads();

    int j0 = colBase + threadIdx.x;
    int j1 = j0 + TPB;
    float4 ep0 = g_ep[j0];
    float4 ep1 = g_ep[j1];

    float s0 = 0.0f, s1 = 0.0f;
#pragma unroll 8
    for (int t = 0; t < ICHUNK; ++t) {
        float4 zp = s_zp[t];                     // broadcast LDS.128
        float arg0 = fmaf(zp.z, ep0.y, fmaf(zp.y, ep0.x, zp.x + ep0.z));
        float arg1 = fmaf(zp.z, ep1.y, fmaf(zp.y, ep1.x, zp.x + ep1.z));
        s0 += ex2(arg0);
        s1 += ex2(arg1);
    }

    g_part[blockIdx.y * N_E + j0] = s0;          // deterministic: unique slot
    g_part[blockIdx.y * N_E + j1] = s1;
}

// ---------------------------------------------------------------------------
// Column sum over i-chunks + log  -> lse_j
// ---------------------------------------------------------------------------
__global__ void colsum_kernel() {
    int j = blockIdx.x * blockDim.x + threadIdx.x;
    if (j >= N_E) return;
    float acc = 0.0f;
#pragma unroll
    for (int c = 0; c < NCHUNK; ++c)
        acc += g_part[c * N_E + j];
    g_lse[j] = __logf(acc);
}

// ---------------------------------------------------------------------------
// Final scalar: loss = -mean(lse) + 0.5*z_dim*(2*ls - 1) + log(N)
// z_dim = 2  ->  + (2*ls - 1)
// ---------------------------------------------------------------------------
__global__ void final_kernel(const float* __restrict__ log_sigma,
                             float* __restrict__ out) {
    __shared__ float red[32];
    int tid = threadIdx.x;                       // 1024 threads
    float local = 0.0f;
    for (int j = tid; j < N_E; j += 1024)
        local += g_lse[j];
#pragma unroll
    for (int o = 16; o > 0; o >>= 1)
        local += __shfl_xor_sync(0xffffffffu, local, o);
    if ((tid & 31) == 0) red[tid >> 5] = local;
    __syncthreads();
    if (tid < 32) {
        float v = red[tid];
#pragma unroll
        for (int o = 16; o > 0; o >>= 1)
            v += __shfl_xor_sync(0xffffffffu, v, o);
        if (tid == 0) {
            float ls = log_sigma[0];
            out[0] = -v / (float)N_E + (2.0f * ls - 1.0f) + logf((float)N_Z);
        }
    }
}

// ---------------------------------------------------------------------------
extern "C" void kernel_launch(void* const* d_in, const int* in_sizes, int n_in,
                              void* d_out, int out_size) {
    const float* z    = (const float*)d_in[0];
    const float* emb  = (const float*)d_in[1];
    const float* ls   = (const float*)d_in[2];
    const float* eps  = (const float*)d_in[3];
    const float* temp = (const float*)d_in[4];
    float* out = (float*)d_out;

    prep_kernel<<<(N_E + 255) / 256, 256>>>(z, emb, ls, eps, temp);

    dim3 grid(N_E / (TPB * COLS), NCHUNK);       // (32, 16) = 512 blocks
    main_kernel<<<grid, TPB>>>();

    colsum_kernel<<<N_E / 256, 256>>>();
    final_kernel<<<1, 1024>>>(ls, out);
}

// round 4
// speedup vs baseline: 1.0770x; 1.0770x over previous
#include <cuda_runtime.h>

#define N_Z    8192
#define N_E    16384
#define M_PER  1024        // M // N_EMB
#define TPB    256
#define COLS   2           // columns per thread
#define ICHUNK 512
#define NCHUNK (N_Z / ICHUNK)   // 16
#define FBLK   (N_E / 256)      // 64 finish blocks

// Scratch (no device allocation allowed -> __device__ globals)
__device__ float g_part[NCHUNK * N_E];   // per-(ichunk, column) partial sums
__device__ float g_bsum[FBLK];           // per-finish-block lse sums
__device__ int   g_cnt = 0;              // last-block arrival counter

__device__ __forceinline__ float ex2(float x) {
    float r;
    asm("ex2.approx.f32 %0, %1;" : "=f"(r) : "f"(x));
    return r;
}

// ---------------------------------------------------------------------------
// Main: each thread owns 2 columns, loops an ICHUNK of i staged in shared.
// Coefficients computed inline (no prep kernel):
//   arg(i,j) = a_i + c_j + b0_i*e0_j + b1_i*e1_j   (log2 domain, al = alpha*log2e)
// MUFU.EX2-bound by design.
// ---------------------------------------------------------------------------
__global__ void __launch_bounds__(TPB) main_kernel(
        const float* __restrict__ z,
        const float* __restrict__ emb,
        const float* __restrict__ log_sigma,
        const float* __restrict__ eps,
        const float* __restrict__ temp) {
    __shared__ float4 s_zp[ICHUNK];

    float T  = __ldg(temp);
    float ls = __ldg(log_sigma);
    const float LOG2E = 1.4426950408889634f;
    // alpha = -1/(2*sigma^2) = -0.5*exp(-2*ls);  al = alpha*log2e
    float al = -0.5f * LOG2E * __expf(-2.0f * ls);

    int ibase = blockIdx.y * ICHUNK;

    // stage z coefficients for this i-chunk (coalesced float2 loads, L2-hot)
    for (int t = threadIdx.x; t < ICHUNK; t += TPB) {
        float z0 = z[2 * (ibase + t) + 0];
        float z1 = z[2 * (ibase + t) + 1];
        s_zp[t] = make_float4(al * (z0 * z0 + z1 * z1),
                              -2.0f * al * z0,
                              -2.0f * al * z1, 0.0f);
    }

    // per-thread column coefficients (inline prep)
    int j0 = blockIdx.x * (TPB * COLS) + threadIdx.x;
    int j1 = j0 + TPB;
    float omT = 1.0f - T;

    int k0 = j0 >> 10, m0 = j0 & (M_PER - 1);
    float e00 = omT * emb[2 * k0 + 0] + T * eps[2 * m0 + 0];
    float e01 = omT * emb[2 * k0 + 1] + T * eps[2 * m0 + 1];
    float c0  = al * (e00 * e00 + e01 * e01);

    int k1 = j1 >> 10, m1 = j1 & (M_PER - 1);
    float e10 = omT * emb[2 * k1 + 0] + T * eps[2 * m1 + 0];
    float e11 = omT * emb[2 * k1 + 1] + T * eps[2 * m1 + 1];
    float c1  = al * (e10 * e10 + e11 * e11);

    __syncthreads();

    float s0 = 0.0f, s1 = 0.0f;
#pragma unroll 8
    for (int t = 0; t < ICHUNK; ++t) {
        float4 zp = s_zp[t];                     // broadcast LDS.128
        float arg0 = fmaf(zp.z, e01, fmaf(zp.y, e00, zp.x + c0));
        float arg1 = fmaf(zp.z, e11, fmaf(zp.y, e10, zp.x + c1));
        s0 += ex2(arg0);
        s1 += ex2(arg1);
    }

    g_part[blockIdx.y * N_E + j0] = s0;          // deterministic: unique slot
    g_part[blockIdx.y * N_E + j1] = s1;
}

// ---------------------------------------------------------------------------
// Finish: column sum over i-chunks + log -> lse_j, block-reduce lse, and the
// LAST block folds the 64 block sums into the final scalar (deterministic
// fixed-order reduction; int atomic only used as an arrival counter).
// ---------------------------------------------------------------------------
__global__ void __launch_bounds__(256) finish_kernel(
        const float* __restrict__ log_sigma,
        float* __restrict__ out) {
    __shared__ float red[8];
    __shared__ int is_last;

    int tid = threadIdx.x;
    int j = blockIdx.x * 256 + tid;

    float acc = 0.0f;
#pragma unroll
    for (int c = 0; c < NCHUNK; ++c)
        acc += g_part[c * N_E + j];
    float l = __logf(acc);

    // block reduction of l
#pragma unroll
    for (int o = 16; o > 0; o >>= 1)
        l += __shfl_xor_sync(0xffffffffu, l, o);
    if ((tid & 31) == 0) red[tid >> 5] = l;
    __syncthreads();
    if (tid < 32) {
        float v = (tid < 8) ? red[tid] : 0.0f;
#pragma unroll
        for (int o = 4; o > 0; o >>= 1)
            v += __shfl_xor_sync(0xffffffffu, v, o);
        if (tid == 0) {
            g_bsum[blockIdx.x] = v;
            __threadfence();
            int prev = atomicAdd(&g_cnt, 1);
            is_last = (prev == FBLK - 1) ? 1 : 0;
        }
    }
    __syncthreads();

    if (is_last && tid < 32) {
        // fixed-order pairwise fold: deterministic
        float v = g_bsum[tid] + g_bsum[tid + 32];
#pragma unroll
        for (int o = 16; o > 0; o >>= 1)
            v += __shfl_xor_sync(0xffffffffu, v, o);
        if (tid == 0) {
            float ls = __ldg(log_sigma);
            // loss = -mean(lse) + 0.5*z_dim*(2*ls - 1) + log(N), z_dim = 2
            out[0] = -v / (float)N_E + (2.0f * ls - 1.0f) + logf((float)N_Z);
            g_cnt = 0;                           // reset for next replay
        }
    }
}

// ---------------------------------------------------------------------------
extern "C" void kernel_launch(void* const* d_in, const int* in_sizes, int n_in,
                              void* d_out, int out_size) {
    const float* z    = (const float*)d_in[0];
    const float* emb  = (const float*)d_in[1];
    const float* ls   = (const float*)d_in[2];
    const float* eps  = (const float*)d_in[3];
    const float* temp = (const float*)d_in[4];
    float* out = (float*)d_out;

    dim3 grid(N_E / (TPB * COLS), NCHUNK);       // (32, 16) = 512 blocks
    main_kernel<<<grid, TPB>>>(z, emb, ls, eps, temp);

    finish_kernel<<<FBLK, 256>>>(ls, out);
}

// round 5
// speedup vs baseline: 1.4003x; 1.3003x over previous
#include <cuda_runtime.h>

#define N_Z     8192
#define N_E     16384
#define M_PER   1024          // M // N_EMB
#define TPB     256
#define COLS    4             // columns per thread
#define JGRP    16            // column groups: N_E / (TPB*COLS)
#define JGW     (TPB * COLS)  // 1024 columns per group
#define ISLICE  18            // i-slices -> 16*18 = 288 blocks (all co-resident)
#define ICHUNK  512           // smem staging chunk

// Scratch (no device allocation allowed -> __device__ globals)
__device__ float g_part[ISLICE * N_E];   // per-(islice, column) partial sums
__device__ float g_jgsum[JGRP];          // per-jg sum of lse
__device__ int   g_cnt_jg[JGRP];         // per-jg slice arrival counters (init 0)
__device__ int   g_cnt = 0;              // jg arrival counter

__device__ __forceinline__ float ex2(float x) {
    float r;
    asm("ex2.approx.f32 %0, %1;" : "=f"(r) : "f"(x));
    return r;
}

// ---------------------------------------------------------------------------
// Fused kernel.
// Phase 1 (all 288 blocks): tile (i-slice x 1024 cols) of
//     exp2( a_i + b0_i*e0_j + b1_i*e1_j )          [c_j folded OUT of loop]
//   accumulated per column into g_part[slice][j].
// Phase 2 (last slice-block per jg): column sums + lse_j = c_j*ln2 + log(S_j),
//   block-reduce -> g_jgsum[jg].
// Phase 3 (last jg): fixed-order fold of 16 jg sums -> loss scalar.
// ---------------------------------------------------------------------------
__global__ void __launch_bounds__(TPB, 2) fused_kernel(
        const float* __restrict__ z,
        const float* __restrict__ emb,
        const float* __restrict__ log_sigma,
        const float* __restrict__ eps,
        const float* __restrict__ temp,
        float* __restrict__ out) {
    __shared__ float4 s_zp[ICHUNK];
    __shared__ float  red[8];
    __shared__ int    s_flag;

    const int tid = threadIdx.x;
    const int jg  = blockIdx.x;          // 0..15
    const int sl  = blockIdx.y;          // 0..17

    const float T  = __ldg(temp);
    const float ls = __ldg(log_sigma);
    const float LOG2E = 1.4426950408889634f;
    const float LN2   = 0.6931471805599453f;
    // alpha = -0.5*exp(-2*ls);  al = alpha * log2(e)
    const float al = -0.5f * LOG2E * __expf(-2.0f * ls);
    const float omT = 1.0f - T;

    // --- per-thread column coefficients (4 columns) ---
    const int jbase = jg * JGW + tid;
    float e0c[COLS], e1c[COLS];
#pragma unroll
    for (int k = 0; k < COLS; ++k) {
        int j = jbase + k * TPB;
        int ke = j >> 10;                // embedding index (M_PER = 1024)
        int m  = j & (M_PER - 1);
        e0c[k] = omT * emb[2 * ke + 0] + T * eps[2 * m + 0];
        e1c[k] = omT * emb[2 * ke + 1] + T * eps[2 * m + 1];
    }

    // --- i-slice bounds: 8192 = 18*455 + 2 ---
    const int i0 = sl * 455 + min(sl, 2);
    const int i1 = i0 + 455 + (sl < 2 ? 1 : 0);

    float s0 = 0.0f, s1 = 0.0f, s2 = 0.0f, s3 = 0.0f;

    for (int base = i0; base < i1; base += ICHUNK) {
        const int len = min(ICHUNK, i1 - base);
        __syncthreads();
        for (int t = tid; t < len; t += TPB) {
            float z0 = z[2 * (base + t) + 0];
            float z1 = z[2 * (base + t) + 1];
            s_zp[t] = make_float4(al * (z0 * z0 + z1 * z1),
                                  -2.0f * al * z0,
                                  -2.0f * al * z1, 0.0f);
        }
        __syncthreads();

#pragma unroll 8
        for (int t = 0; t < len; ++t) {
            float4 zp = s_zp[t];                 // broadcast LDS.128
            float g0 = fmaf(zp.z, e1c[0], fmaf(zp.y, e0c[0], zp.x));
            float g1 = fmaf(zp.z, e1c[1], fmaf(zp.y, e0c[1], zp.x));
            float g2 = fmaf(zp.z, e1c[2], fmaf(zp.y, e0c[2], zp.x));
            float g3 = fmaf(zp.z, e1c[3], fmaf(zp.y, e0c[3], zp.x));
            s0 += ex2(g0);
            s1 += ex2(g1);
            s2 += ex2(g2);
            s3 += ex2(g3);
        }
    }

    // --- write partials (unique slots: deterministic) ---
    g_part[sl * N_E + jbase + 0 * TPB] = s0;
    g_part[sl * N_E + jbase + 1 * TPB] = s1;
    g_part[sl * N_E + jbase + 2 * TPB] = s2;
    g_part[sl * N_E + jbase + 3 * TPB] = s3;

    // --- arrival: last slice-block of this jg does the column reduction ---
    __syncthreads();
    if (tid == 0) {
        __threadfence();
        int prev = atomicAdd(&g_cnt_jg[jg], 1);
        s_flag = (prev == ISLICE - 1) ? 1 : 0;
    }
    __syncthreads();
    if (!s_flag) return;
    __threadfence();                         // acquire partials from other blocks

    // Phase 2: lse over this jg's 1024 columns (same column mapping as phase 1,
    // so e0c/e1c are already in registers -> c_j recomputed for free).
    float lsum = 0.0f;
#pragma unroll
    for (int k = 0; k < COLS; ++k) {
        int j = jbase + k * TPB;
        float S = 0.0f;
#pragma unroll
        for (int s = 0; s < ISLICE; ++s)
            S += g_part[s * N_E + j];
        float c = al * (e0c[k] * e0c[k] + e1c[k] * e1c[k]);
        lsum += c * LN2 + __logf(S);         // lse_j
    }

    // block reduction of lsum (256 threads)
#pragma unroll
    for (int o = 16; o > 0; o >>= 1)
        lsum += __shfl_xor_sync(0xffffffffu, lsum, o);
    if ((tid & 31) == 0) red[tid >> 5] = lsum;
    __syncthreads();
    if (tid == 0) {
        float v = red[0];
#pragma unroll
        for (int w = 1; w < 8; ++w) v += red[w];
        g_jgsum[jg] = v;
        g_cnt_jg[jg] = 0;                    // reset for next graph replay
        __threadfence();
        int prev = atomicAdd(&g_cnt, 1);
        s_flag = (prev == JGRP - 1) ? 2 : 0;
    }
    __syncthreads();
    if (s_flag != 2) return;

    // Phase 3: final scalar (fixed-order fold over 16 jg sums)
    if (tid == 0) {
        __threadfence();
        float v = 0.0f;
#pragma unroll
        for (int g = 0; g < JGRP; ++g) v += g_jgsum[g];
        // loss = -mean(lse) + 0.5*z_dim*(2*ls - 1) + log(N), z_dim = 2
        out[0] = -v / (float)N_E + (2.0f * ls - 1.0f) + logf((float)N_Z);
        g_cnt = 0;                           // reset for next graph replay
    }
}

// ---------------------------------------------------------------------------
extern "C" void kernel_launch(void* const* d_in, const int* in_sizes, int n_in,
                              void* d_out, int out_size) {
    const float* z    = (const float*)d_in[0];
    const float* emb  = (const float*)d_in[1];
    const float* ls   = (const float*)d_in[2];
    const float* eps  = (const float*)d_in[3];
    const float* temp = (const float*)d_in[4];
    float* out = (float*)d_out;

    dim3 grid(JGRP, ISLICE);                 // (16, 18) = 288 blocks
    fused_kernel<<<grid, TPB>>>(z, emb, ls, eps, temp, out);
}

// round 9
// speedup vs baseline: 2.6358x; 1.8823x over previous
#include <cuda_runtime.h>

#define N_Z    8192
#define N_E    16384
#define N_EMBS 16
#define M_PER  1024
#define TPB    256
#define MG     4          // m-groups of 256 columns
#define NSL    64         // i-slices of 128
#define ICH    128
#define NBLK   (MG * NSL) // 256 blocks, all co-resident at occ>=2

// Scratch (__device__ globals; no allocation allowed)
__device__ float g_part[NSL][N_EMBS][M_PER];  // partial S per (slice,k,m)  (4MB)
__device__ float g_bsum[64];
__device__ int   g_bar1 = 0;
__device__ int   g_bar2 = 0;

__device__ __forceinline__ float ex2(float x) {
    float r; asm("ex2.approx.f32 %0, %1;" : "=f"(r) : "f"(x)); return r;
}
__device__ __forceinline__ unsigned long long fma2(unsigned long long a,
                                                   unsigned long long b,
                                                   unsigned long long c) {
    unsigned long long d;
    asm("fma.rn.f32x2 %0, %1, %2, %3;" : "=l"(d) : "l"(a), "l"(b), "l"(c));
    return d;
}

// ---------------------------------------------------------------------------
// Single persistent kernel.
// Phase 1: block (mg, sl) computes, for its 256 m-columns and 128 i-rows,
//   acc_k[m] += G[i][k] * D[i][m]    (G staged in smem, 16-wide rows)
//   where G = exp2(a_i + b_i.u_k), D = exp2(b_i.v_m)   [log2 domain]
// Grid barrier (all 256 blocks resident).
// Phase 2: blocks 0..63 reduce slices, apply C_{k,m} in log domain -> lse,
//   block-reduce. Barrier 2: block 0 folds 64 sums -> loss scalar.
// ---------------------------------------------------------------------------
__global__ void __launch_bounds__(TPB, 2) fused_kernel(
        const float* __restrict__ z,
        const float* __restrict__ emb,
        const float* __restrict__ log_sigma,
        const float* __restrict__ eps,
        const float* __restrict__ temp,
        float* __restrict__ out) {
    __shared__ float4 s_G[ICH][4];    // 16 G values per i (as 4 float4)
    __shared__ float2 s_b[ICH];       // (b0,b1) per i
    __shared__ float  red[8];

    const int tid = threadIdx.x;
    const int mg  = blockIdx.x;       // 0..3
    const int sl  = blockIdx.y;       // 0..63
    const int bid = sl * MG + mg;

    const float T  = __ldg(temp);
    const float ls = __ldg(log_sigma);
    const float LOG2E = 1.4426950408889634f;
    const float LN2   = 0.6931471805599453f;
    const float al  = -0.5f * LOG2E * __expf(-2.0f * ls);  // alpha*log2e
    const float omT = 1.0f - T;

    // ---- stage: 2 threads per i (each does 8 of the 16 k's) ----
    {
        int il = tid >> 1;
        int h  = tid & 1;
        int i  = sl * ICH + il;
        float z0 = z[2 * i + 0], z1 = z[2 * i + 1];
        float a  = al * (z0 * z0 + z1 * z1);
        float b0 = -2.0f * al * z0;
        float b1 = -2.0f * al * z1;
        if (h == 0) s_b[il] = make_float2(b0, b1);
        float g[8];
#pragma unroll
        for (int kk = 0; kk < 8; ++kk) {
            int k = h * 8 + kk;
            float u0 = omT * emb[2 * k + 0];
            float u1 = omT * emb[2 * k + 1];
            g[kk] = ex2(fmaf(b1, u1, fmaf(b0, u0, a)));
        }
        s_G[il][2 * h + 0] = make_float4(g[0], g[1], g[2], g[3]);
        s_G[il][2 * h + 1] = make_float4(g[4], g[5], g[6], g[7]);
    }

    const int m  = mg * TPB + tid;                 // this thread's column
    const float v0 = T * eps[2 * m + 0];
    const float v1 = T * eps[2 * m + 1];
    __syncthreads();

    // ---- main loop: 128 i, 16 k-accumulators packed as 8 f32x2 ----
    unsigned long long acc[8];
#pragma unroll
    for (int p = 0; p < 8; ++p) acc[p] = 0ULL;

#pragma unroll 8
    for (int t = 0; t < ICH; ++t) {
        float2 b = s_b[t];                          // broadcast LDS.64
        float D = ex2(fmaf(b.y, v1, b.x * v0));
        unsigned int Du = __float_as_uint(D);
        unsigned long long D2;
        asm("mov.b64 %0, {%1, %2};" : "=l"(D2) : "r"(Du), "r"(Du));
        const ulonglong2* G = reinterpret_cast<const ulonglong2*>(&s_G[t][0]);
        ulonglong2 gA = G[0], gB = G[1], gC = G[2], gD = G[3];
        acc[0] = fma2(gA.x, D2, acc[0]);
        acc[1] = fma2(gA.y, D2, acc[1]);
        acc[2] = fma2(gB.x, D2, acc[2]);
        acc[3] = fma2(gB.y, D2, acc[3]);
        acc[4] = fma2(gC.x, D2, acc[4]);
        acc[5] = fma2(gC.y, D2, acc[5]);
        acc[6] = fma2(gD.x, D2, acc[6]);
        acc[7] = fma2(gD.y, D2, acc[7]);
    }

    // write partials (unique slots -> deterministic)
#pragma unroll
    for (int p = 0; p < 8; ++p) {
        unsigned int lo, hi;
        asm("mov.b64 {%0, %1}, %2;" : "=r"(lo), "=r"(hi) : "l"(acc[p]));
        g_part[sl][2 * p + 0][m] = __uint_as_float(lo);
        g_part[sl][2 * p + 1][m] = __uint_as_float(hi);
    }

    // ---- grid barrier 1 (all 256 blocks are co-resident) ----
    __syncthreads();
    if (tid == 0) {
        __threadfence();
        atomicAdd(&g_bar1, 1);
        while (*(volatile int*)&g_bar1 < NBLK) __nanosleep(32);
    }
    __syncthreads();

    // ---- phase 2: 64 blocks, 256 columns each ----
    if (bid < 64) {
        int j  = bid * TPB + tid;
        int k  = j >> 10;
        int mm = j & (M_PER - 1);
        float S = 0.0f;
#pragma unroll
        for (int s = 0; s < NSL; ++s)
            S += __ldcg(&g_part[s][k][mm]);
        float u0 = omT * emb[2 * k + 0], u1 = omT * emb[2 * k + 1];
        float w0 = u0 + T * eps[2 * mm + 0];
        float w1 = u1 + T * eps[2 * mm + 1];
        float lse = LN2 * (al * (w0 * w0 + w1 * w1)) + __logf(S);

#pragma unroll
        for (int o = 16; o > 0; o >>= 1)
            lse += __shfl_xor_sync(0xffffffffu, lse, o);
        if ((tid & 31) == 0) red[tid >> 5] = lse;
        __syncthreads();
        if (tid == 0) {
            float v = red[0];
#pragma unroll
            for (int w = 1; w < 8; ++w) v += red[w];
            g_bsum[bid] = v;
        }
    }

    // ---- barrier 2 + final fold by block 0 ----
    __syncthreads();
    if (tid == 0) {
        __threadfence();
        atomicAdd(&g_bar2, 1);
        if (bid == 0) {
            while (*(volatile int*)&g_bar2 < NBLK) __nanosleep(32);
            float v = 0.0f;
#pragma unroll
            for (int b = 0; b < 64; ++b) v += __ldcg(&g_bsum[b]);
            // loss = -mean(lse) + 0.5*z_dim*(2*ls - 1) + log(N), z_dim = 2
            out[0] = -v / (float)N_E + (2.0f * ls - 1.0f) + logf((float)N_Z);
            g_bar1 = 0;                       // reset for next graph replay
            g_bar2 = 0;
            __threadfence();
        }
    }
}

// ---------------------------------------------------------------------------
extern "C" void kernel_launch(void* const* d_in, const int* in_sizes, int n_in,
                              void* d_out, int out_size) {
    const float* z    = (const float*)d_in[0];
    const float* emb  = (const float*)d_in[1];
    const float* ls   = (const float*)d_in[2];
    const float* eps  = (const float*)d_in[3];
    const float* temp = (const float*)d_in[4];
    float* out = (float*)d_out;

    dim3 grid(MG, NSL);                       // (4, 64) = 256 blocks
    fused_kernel<<<grid, TPB>>>(z, emb, ls, eps, temp, out);
}